// round 16
// baseline (speedup 1.0000x reference)
#include <cuda_runtime.h>
#include <cuda_bf16.h>

// Two-link planar arm forward dynamics, folded constants:
//   alpha = 1.7, beta = 0.5, delta = 0.35 (== M22, constant)
//   g1 coefs: 1.5*9.81 = 14.715 ; 0.5*9.81 = 4.905
#define K_ALPHA 1.7f
#define K_BETA  0.5f
#define K_DELTA 0.35f
#define K_G1A   14.715f
#define K_G12   4.905f

__device__ __forceinline__ float2 qdd_row(float q1, float q2,
                                          float dq1, float dq2,
                                          float t1, float t2) {
    float s2, c2;
    __sincosf(q2, &s2, &c2);
    float c1  = __cosf(q1);
    float c12 = __cosf(q1 + q2);

    float M11 = fmaf(2.0f * K_BETA, c2, K_ALPHA);
    float M12 = fmaf(K_BETA, c2, K_DELTA);

    float g1 = fmaf(K_G1A, c1, K_G12 * c12);
    float g2 = K_G12 * c12;

    float cor = fmaf(2.0f * dq1, dq2, dq2 * dq2);
    float h1 = fmaf(-K_BETA * s2, cor, g1);
    float h2 = fmaf(K_BETA * s2, dq1 * dq1, g2);

    float r1 = t1 - h1;
    float r2 = t2 - h2;

    float det  = fmaf(M11, K_DELTA, -M12 * M12);  // >= 0.2225, well conditioned
    float rdet = __frcp_rn(det);

    float o1 = fmaf(K_DELTA, r1, -M12 * r2) * rdet;
    float o2 = fmaf(M11,     r2, -M12 * r1) * rdet;
    return make_float2(o1, o2);
}

// Same per-thread body as the frozen best (2 rows/thread, 3x front-batched
// streaming LDG.128, write-through STG.128, 24 regs) at the one unmeasured
// CTA size: 128 threads. Finer scheduling granularity, narrower per-CTA
// load bursts at the L1tex queue, same occupancy budget.
__global__ __launch_bounds__(128) void fd_qdd_kernel(
    const float4* __restrict__ q4,
    const float4* __restrict__ dq4,
    const float4* __restrict__ tau4,
    float4* __restrict__ out4,
    int n4)  // n4 = B/2
{
    int i = blockIdx.x * blockDim.x + threadIdx.x;
    if (i >= n4) return;

    // Front-batch the three independent 128-bit streaming loads (MLP=3).
    float4 qv  = __ldcs(&q4[i]);
    float4 dqv = __ldcs(&dq4[i]);
    float4 tv  = __ldcs(&tau4[i]);

    float2 a = qdd_row(qv.x, qv.y, dqv.x, dqv.y, tv.x, tv.y);
    float2 b = qdd_row(qv.z, qv.w, dqv.z, dqv.w, tv.z, tv.w);

    __stwt(&out4[i], make_float4(a.x, a.y, b.x, b.y));
}

// Tail handler for odd row counts (B here is even; kept for generality).
__global__ void fd_qdd_tail_kernel(
    const float2* __restrict__ q2,
    const float2* __restrict__ dq2,
    const float2* __restrict__ tau2,
    float2* __restrict__ out2,
    int start, int nrows)
{
    int i = start + blockIdx.x * blockDim.x + threadIdx.x;
    if (i >= nrows) return;
    float2 qv = q2[i], dv = dq2[i], tv = tau2[i];
    out2[i] = qdd_row(qv.x, qv.y, dv.x, dv.y, tv.x, tv.y);
}

extern "C" void kernel_launch(void* const* d_in, const int* in_sizes, int n_in,
                              void* d_out, int out_size) {
    const float* q   = (const float*)d_in[0];
    const float* dq  = (const float*)d_in[1];
    const float* tau = (const float*)d_in[2];
    float* out = (float*)d_out;

    int nrows = in_sizes[0] / 2;     // B
    int n4 = nrows / 2;              // float4 tiles (2 rows each)

    if (n4 > 0) {
        const int threads = 128;
        int blocks = (n4 + threads - 1) / threads;
        fd_qdd_kernel<<<blocks, threads>>>(
            (const float4*)q, (const float4*)dq, (const float4*)tau,
            (float4*)out, n4);
    }
    int done = n4 * 2;
    if (done < nrows) {
        int rem = nrows - done;
        fd_qdd_tail_kernel<<<(rem + 127) / 128, 128>>>(
            (const float2*)q, (const float2*)dq, (const float2*)tau,
            (float2*)out, done, nrows);
    }
}

// round 17
// speedup vs baseline: 1.0317x; 1.0317x over previous
#include <cuda_runtime.h>
#include <cuda_bf16.h>

// Two-link planar arm forward dynamics, folded constants:
//   alpha = 1.7, beta = 0.5, delta = 0.35 (== M22, constant)
//   g1 coefs: 1.5*9.81 = 14.715 ; 0.5*9.81 = 4.905
#define K_ALPHA 1.7f
#define K_BETA  0.5f
#define K_DELTA 0.35f
#define K_G1A   14.715f
#define K_G12   4.905f

__device__ __forceinline__ float2 qdd_row(float q1, float q2,
                                          float dq1, float dq2,
                                          float t1, float t2) {
    float s2, c2;
    __sincosf(q2, &s2, &c2);
    float c1  = __cosf(q1);
    float c12 = __cosf(q1 + q2);

    float M11 = fmaf(2.0f * K_BETA, c2, K_ALPHA);
    float M12 = fmaf(K_BETA, c2, K_DELTA);

    float g1 = fmaf(K_G1A, c1, K_G12 * c12);
    float g2 = K_G12 * c12;

    float cor = fmaf(2.0f * dq1, dq2, dq2 * dq2);
    float h1 = fmaf(-K_BETA * s2, cor, g1);
    float h2 = fmaf(K_BETA * s2, dq1 * dq1, g2);

    float r1 = t1 - h1;
    float r2 = t2 - h2;

    float det  = fmaf(M11, K_DELTA, -M12 * M12);  // >= 0.2225, well conditioned
    float rdet = __frcp_rn(det);

    float o1 = fmaf(K_DELTA, r1, -M12 * r2) * rdet;
    float o2 = fmaf(M11,     r2, -M12 * r1) * rdet;
    return make_float2(o1, o2);
}

// FINAL frozen operating point (measured optimum over R3-R15):
//   2 rows/thread, 3x front-batched streaming LDG.128 (__ldcs),
//   write-through STG.128 (__stwt), 24 regs, 256-thread blocks.
// Measured: dur_us 41.44 (x3 reproduced), HBM ~6.5 TB/s (82% of spec),
// occ ~82-85%, issue ~34-38%, rel_err 4.0e-7.
// CTA-size sweep: 128->77.4% DRAM, 256->82.5%, 512->79.9%. All
// register-buying MLP variants (4 rows, prefetch, persistent) lost
// occupancy and DRAM%. Traffic is compulsory; this is the roofline.
__global__ __launch_bounds__(256) void fd_qdd_kernel(
    const float4* __restrict__ q4,
    const float4* __restrict__ dq4,
    const float4* __restrict__ tau4,
    float4* __restrict__ out4,
    int n4)  // n4 = B/2
{
    int i = blockIdx.x * blockDim.x + threadIdx.x;
    if (i >= n4) return;

    // Front-batch the three independent 128-bit streaming loads (MLP=3).
    float4 qv  = __ldcs(&q4[i]);
    float4 dqv = __ldcs(&dq4[i]);
    float4 tv  = __ldcs(&tau4[i]);

    float2 a = qdd_row(qv.x, qv.y, dqv.x, dqv.y, tv.x, tv.y);
    float2 b = qdd_row(qv.z, qv.w, dqv.z, dqv.w, tv.z, tv.w);

    __stwt(&out4[i], make_float4(a.x, a.y, b.x, b.y));
}

// Tail handler for odd row counts (B here is even; kept for generality).
__global__ void fd_qdd_tail_kernel(
    const float2* __restrict__ q2,
    const float2* __restrict__ dq2,
    const float2* __restrict__ tau2,
    float2* __restrict__ out2,
    int start, int nrows)
{
    int i = start + blockIdx.x * blockDim.x + threadIdx.x;
    if (i >= nrows) return;
    float2 qv = q2[i], dv = dq2[i], tv = tau2[i];
    out2[i] = qdd_row(qv.x, qv.y, dv.x, dv.y, tv.x, tv.y);
}

extern "C" void kernel_launch(void* const* d_in, const int* in_sizes, int n_in,
                              void* d_out, int out_size) {
    const float* q   = (const float*)d_in[0];
    const float* dq  = (const float*)d_in[1];
    const float* tau = (const float*)d_in[2];
    float* out = (float*)d_out;

    int nrows = in_sizes[0] / 2;     // B
    int n4 = nrows / 2;              // float4 tiles (2 rows each)

    if (n4 > 0) {
        const int threads = 256;
        int blocks = (n4 + threads - 1) / threads;
        fd_qdd_kernel<<<blocks, threads>>>(
            (const float4*)q, (const float4*)dq, (const float4*)tau,
            (float4*)out, n4);
    }
    int done = n4 * 2;
    if (done < nrows) {
        int rem = nrows - done;
        fd_qdd_tail_kernel<<<(rem + 127) / 128, 128>>>(
            (const float2*)q, (const float2*)dq, (const float2*)tau,
            (float2*)out, done, nrows);
    }
}